// round 15
// baseline (speedup 1.0000x reference)
#include <cuda_runtime.h>
#include <cuda_fp16.h>
#include <cstdint>

#define N_ATOMS   131072
#define N_EDGES   1048576
#define DSTATE    64
#define N_MOLS    4096
#define ETILE     128
#define N_ETILES  (N_EDGES / ETILE)   // 8192
#define N_ATILES  (N_ATOMS / 128)     // 1024

__device__ float4 g_new_states4[N_ATOMS * DSTATE / 4];
__device__ uint4  g_Ph4[N_ATOMS * 8];   // P as fp16: 64 halfs = 8 uint4 per atom
__device__ uint4  g_Qh4[N_ATOMS * 8];

__device__ __forceinline__ uint32_t smem_u32(const void* p) {
    uint32_t a;
    asm("{ .reg .u64 t; cvta.to.shared.u64 t, %1; cvt.u32.u64 %0, t; }" : "=r"(a) : "l"(p));
    return a;
}

// fp16 m16n8k16, fp32 accum
__device__ __forceinline__ void mma16(float* c, unsigned a0, unsigned a1,
                                      unsigned a2, unsigned a3,
                                      unsigned b0, unsigned b1) {
    asm volatile(
        "mma.sync.aligned.m16n8k16.row.col.f32.f16.f16.f32 "
        "{%0,%1,%2,%3}, {%4,%5,%6,%7}, {%8,%9}, {%0,%1,%2,%3};"
        : "+f"(c[0]), "+f"(c[1]), "+f"(c[2]), "+f"(c[3])
        : "r"(a0), "r"(a1), "r"(a2), "r"(a3), "r"(b0), "r"(b1));
}

__device__ __forceinline__ unsigned packh2(float lo, float hi) {
    __half2 h = __floats2half2_rn(lo, hi);
    return *(unsigned*)&h;
}

// ====================== P/Q precompute: merged passes, direct-global fragments ======================
// smem: only fp16 weights (2 x 64 x 36 uints = 18 KB). No per-tile barriers.
#define PQ_WT   0
#define PQ_WB   (64*36)
#define PQ_UINTS (2*64*36)
#define PQ_SMEM_BYTES (PQ_UINTS * 4)

__global__ void __launch_bounds__(256, 2) pq_kernel(
    const float* __restrict__ atom_states,
    const float* __restrict__ w0)
{
    extern __shared__ unsigned smu[];
    unsigned* Wt = smu + PQ_WT;
    unsigned* Wb = smu + PQ_WB;

    const int tid  = threadIdx.x;
    const int warp = tid >> 5, lane = tid & 31;
    const int g = lane >> 2, t = lane & 3;
    const int wbase = warp * 16;

    for (int i = tid; i < 64 * 64; i += 256) {
        int k = i >> 6, n = i & 63;
        ((__half*)Wt)[n * 72 + k] = __float2half_rn(w0[k * 64 + n]);
        ((__half*)Wb)[n * 72 + k] = __float2half_rn(w0[(k + 64) * 64 + n]);
    }
    __syncthreads();   // only barrier in the kernel

    unsigned* gP = (unsigned*)g_Ph4;
    unsigned* gQ = (unsigned*)g_Qh4;

    for (int tile = blockIdx.x; tile < N_ATILES; tile += gridDim.x) {
        const float* X = atom_states + (size_t)tile * 128 * 64;
        const int row0 = wbase + g;

        float cP[8][4], cQ[8][4];
#pragma unroll
        for (int nt = 0; nt < 8; nt++) {
            cP[nt][0] = cP[nt][1] = cP[nt][2] = cP[nt][3] = 0.f;
            cQ[nt][0] = cQ[nt][1] = cQ[nt][2] = cQ[nt][3] = 0.f;
        }

#pragma unroll
        for (int kt = 0; kt < 4; kt++) {
            const int kb = kt * 8;
            const int k0 = 2 * (kb + t), k1 = 2 * (kb + t + 4);
            const float2 f0 = *(const float2*)(X + (size_t)(row0)     * 64 + k0);
            const float2 f1 = *(const float2*)(X + (size_t)(row0 + 8) * 64 + k0);
            const float2 f2 = *(const float2*)(X + (size_t)(row0)     * 64 + k1);
            const float2 f3 = *(const float2*)(X + (size_t)(row0 + 8) * 64 + k1);
            const unsigned a0 = packh2(f0.x, f0.y);
            const unsigned a1 = packh2(f1.x, f1.y);
            const unsigned a2 = packh2(f2.x, f2.y);
            const unsigned a3 = packh2(f3.x, f3.y);
#pragma unroll
            for (int nt = 0; nt < 8; nt++) {
                const unsigned bt0 = Wt[(nt * 8 + g) * 36 + kb + t];
                const unsigned bt1 = Wt[(nt * 8 + g) * 36 + kb + t + 4];
                mma16(cP[nt], a0, a1, a2, a3, bt0, bt1);
                const unsigned bb0 = Wb[(nt * 8 + g) * 36 + kb + t];
                const unsigned bb1 = Wb[(nt * 8 + g) * 36 + kb + t + 4];
                mma16(cQ[nt], a0, a1, a2, a3, bb0, bb1);
            }
        }

        const size_t ob = (size_t)tile * 128 * 32;
#pragma unroll
        for (int nt = 0; nt < 8; nt++) {
            gP[ob + (size_t)(row0)     * 32 + nt * 4 + t] = packh2(cP[nt][0], cP[nt][1]);
            gP[ob + (size_t)(row0 + 8) * 32 + nt * 4 + t] = packh2(cP[nt][2], cP[nt][3]);
            gQ[ob + (size_t)(row0)     * 32 + nt * 4 + t] = packh2(cQ[nt][0], cQ[nt][1]);
            gQ[ob + (size_t)(row0 + 8) * 32 + nt * 4 + t] = packh2(cQ[nt][2], cQ[nt][3]);
        }

        // zero this warp's 16 rows of g_new (16 rows x 16 float4)
        float4* gz = g_new_states4 + (size_t)tile * 128 * 16 + (size_t)wbase * 16;
        const float4 z = make_float4(0.f, 0.f, 0.f, 0.f);
#pragma unroll
        for (int k = 0; k < 8; k++) gz[k * 32 + lane] = z;
    }
}

// ====================== edge kernel (unchanged from R13/R14) ======================
#define EH_A0   0
#define EH_YS   (128*36)
#define EH_W1   (EH_YS + 128*36)
#define EH_W2   (EH_W1 + 64*36)
#define EH_B0   (EH_W2 + 64*36)
#define EH_B1   (EH_B0 + 64)
#define EH_B2   (EH_B1 + 64)
#define EH_DST  (EH_B2 + 64)
#define EH_SRC  (EH_DST + 128)
#define EH_UINTS (EH_SRC + 128)
#define EH_SMEM_BYTES (EH_UINTS * 4)

__global__ void __launch_bounds__(256, 3) edge_kernel(
    const int* __restrict__ edge_src,
    const int* __restrict__ edge_dst,
    const float* __restrict__ b0,
    const float* __restrict__ w1, const float* __restrict__ b1,
    const float* __restrict__ w2, const float* __restrict__ b2)
{
    extern __shared__ unsigned smu[];
    unsigned* A0u = smu + EH_A0;
    unsigned* Ysu = smu + EH_YS;
    unsigned* W1u = smu + EH_W1;
    unsigned* W2u = smu + EH_W2;
    float* bs0 = (float*)(smu + EH_B0);
    float* bs1 = (float*)(smu + EH_B1);
    float* bs2 = (float*)(smu + EH_B2);
    int* sdst = (int*)(smu + EH_DST);
    int* ssrc = (int*)(smu + EH_SRC);

    const int tid  = threadIdx.x;
    const int warp = tid >> 5, lane = tid & 31;
    const int g = lane >> 2, t = lane & 3;
    const int wbase = warp * 16;

    for (int i = tid; i < 64 * 64; i += 256) {
        int k = i >> 6, n = i & 63;
        ((__half*)W1u)[n * 72 + k] = __float2half_rn(w1[i]);
        ((__half*)W2u)[n * 72 + k] = __float2half_rn(w2[i]);
    }
    if (tid < 64) { bs0[tid] = b0[tid]; bs1[tid] = b1[tid]; bs2[tid] = b2[tid]; }
    __syncthreads();

    const uint4* gP = g_Ph4;
    const uint4* gQ = g_Qh4;
    float* g_new = (float*)g_new_states4;

    for (int tile = blockIdx.x; tile < N_ETILES; tile += gridDim.x) {
        const int e0 = tile * ETILE + wbase;

        if (lane < 16)      sdst[wbase + lane]        = edge_dst[e0 + lane];
        else                ssrc[wbase + (lane - 16)] = edge_src[e0 + lane - 16];
        __syncwarp();

#pragma unroll
        for (int c = 0; c < 4; c++) {
            const int i = c * 32 + lane;
            const int rl = i >> 3, q = i & 7;
            const int r = wbase + rl;
            const uint4 pu = gP[(size_t)sdst[r] * 8 + q];
            const uint4 su = gQ[(size_t)ssrc[r] * 8 + q];
            const __half2* ph = (const __half2*)&pu;
            const __half2* sh = (const __half2*)&su;
            uint4 o;
            unsigned* ou = (unsigned*)&o;
#pragma unroll
            for (int j = 0; j < 4; j++) {
                const float2 pf = __half22float2(ph[j]);
                const float2 sf = __half22float2(sh[j]);
                const int col = q * 8 + 2 * j;
                ou[j] = packh2(fmaxf(pf.x + sf.x + bs0[col],     0.f),
                               fmaxf(pf.y + sf.y + bs0[col + 1], 0.f));
            }
            *(uint4*)(A0u + (size_t)r * 36 + q * 4) = o;
        }
        __syncwarp();

        const int r0 = wbase + g;

        {
            float c[8][4];
#pragma unroll
            for (int nt = 0; nt < 8; nt++) {
                const float2 bb = *(const float2*)(bs1 + nt * 8 + 2 * t);
                c[nt][0] = bb.x; c[nt][1] = bb.y; c[nt][2] = bb.x; c[nt][3] = bb.y;
            }
#pragma unroll
            for (int kt = 0; kt < 4; kt++) {
                const int kb = kt * 8;
                const unsigned a0 = A0u[(r0)     * 36 + kb + t];
                const unsigned a1 = A0u[(r0 + 8) * 36 + kb + t];
                const unsigned a2 = A0u[(r0)     * 36 + kb + t + 4];
                const unsigned a3 = A0u[(r0 + 8) * 36 + kb + t + 4];
#pragma unroll
                for (int nt = 0; nt < 8; nt++) {
                    const unsigned b0r = W1u[(nt * 8 + g) * 36 + kb + t];
                    const unsigned b1r = W1u[(nt * 8 + g) * 36 + kb + t + 4];
                    mma16(c[nt], a0, a1, a2, a3, b0r, b1r);
                }
            }
#pragma unroll
            for (int nt = 0; nt < 8; nt++) {
                Ysu[(r0)     * 36 + nt * 4 + t] =
                    packh2(fmaxf(c[nt][0], 0.f), fmaxf(c[nt][1], 0.f));
                Ysu[(r0 + 8) * 36 + nt * 4 + t] =
                    packh2(fmaxf(c[nt][2], 0.f), fmaxf(c[nt][3], 0.f));
            }
        }
        __syncwarp();

        {
            float c[8][4];
#pragma unroll
            for (int nt = 0; nt < 8; nt++) {
                const float2 bb = *(const float2*)(bs2 + nt * 8 + 2 * t);
                c[nt][0] = bb.x; c[nt][1] = bb.y; c[nt][2] = bb.x; c[nt][3] = bb.y;
            }
#pragma unroll
            for (int kt = 0; kt < 4; kt++) {
                const int kb = kt * 8;
                const unsigned a0 = Ysu[(r0)     * 36 + kb + t];
                const unsigned a1 = Ysu[(r0 + 8) * 36 + kb + t];
                const unsigned a2 = Ysu[(r0)     * 36 + kb + t + 4];
                const unsigned a3 = Ysu[(r0 + 8) * 36 + kb + t + 4];
#pragma unroll
                for (int nt = 0; nt < 8; nt++) {
                    const unsigned b0r = W2u[(nt * 8 + g) * 36 + kb + t];
                    const unsigned b1r = W2u[(nt * 8 + g) * 36 + kb + t + 4];
                    mma16(c[nt], a0, a1, a2, a3, b0r, b1r);
                }
            }
            const int da = sdst[r0], db = sdst[r0 + 8];
#pragma unroll
            for (int nt = 0; nt < 8; nt++) {
                const int col = nt * 8 + 2 * t;
                const float v0 = fmaxf(c[nt][0], 0.f), v1 = fmaxf(c[nt][1], 0.f);
                const float v2 = fmaxf(c[nt][2], 0.f), v3 = fmaxf(c[nt][3], 0.f);
                asm volatile("red.global.add.v2.f32 [%0], {%1,%2};"
                             :: "l"(g_new + (size_t)da * 64 + col), "f"(v0), "f"(v1) : "memory");
                asm volatile("red.global.add.v2.f32 [%0], {%1,%2};"
                             :: "l"(g_new + (size_t)db * 64 + col), "f"(v2), "f"(v3) : "memory");
            }
        }
        __syncwarp();
    }
}

// ====================== readout kernel (fp16, unchanged from R14) ======================
#define RH_XS   0
#define RH_YS   (128*36)
#define RH_W1   (RH_YS + 128*36)
#define RH_W2   (RH_W1 + 64*36)
#define RH_W3   (RH_W2 + 64*36)
#define RH_B1   (RH_W3 + 16*36)
#define RH_B2   (RH_B1 + 64)
#define RH_B3   (RH_B2 + 64)
#define RH_UINTS (RH_B3 + 16)
#define RH_SMEM_BYTES (RH_UINTS * 4)

__global__ void __launch_bounds__(256, 3) readout_kernel(
    const float* __restrict__ fc1w, const float* __restrict__ fc1b,
    const float* __restrict__ fc2w, const float* __restrict__ fc2b,
    const float* __restrict__ outw, const float* __restrict__ outb,
    float* __restrict__ out)
{
    extern __shared__ unsigned smu[];
    unsigned* Xsu = smu + RH_XS;
    unsigned* Ysu = smu + RH_YS;
    float*    Of  = (float*)(smu + RH_YS);
    unsigned* W1u = smu + RH_W1;
    unsigned* W2u = smu + RH_W2;
    unsigned* W3u = smu + RH_W3;
    float* bs1 = (float*)(smu + RH_B1);
    float* bs2 = (float*)(smu + RH_B2);
    float* bs3 = (float*)(smu + RH_B3);

    const int tid  = threadIdx.x;
    const int warp = tid >> 5, lane = tid & 31;
    const int g = lane >> 2, t = lane & 3;

    for (int i = tid; i < 64 * 64; i += 256) {
        int k = i >> 6, n = i & 63;
        ((__half*)W1u)[n * 72 + k] = __float2half_rn(fc1w[i]);
        ((__half*)W2u)[n * 72 + k] = __float2half_rn(fc2w[i]);
    }
    for (int i = tid; i < 64 * 16; i += 256) {
        int k = i >> 4, n = i & 15;
        ((__half*)W3u)[n * 72 + k] = __float2half_rn(outw[i]);
    }
    if (tid < 64) { bs1[tid] = fc1b[tid]; bs2[tid] = fc2b[tid]; }
    if (tid < 16) bs3[tid] = outb[tid];

    const float* g_new = (const float*)g_new_states4;
    const int r0 = warp * 16 + g;

    for (int tile = blockIdx.x; tile < N_ATILES; tile += gridDim.x) {
        __syncthreads();
        for (int i = tid; i < 128 * 16; i += 256) {
            const int rr = i >> 4, q = i & 15;
            const float4 v = *(const float4*)(g_new + ((size_t)tile * 128 + rr) * 64 + q * 4);
            uint2 u;
            u.x = packh2(v.x, v.y);
            u.y = packh2(v.z, v.w);
            *(uint2*)(Xsu + (size_t)rr * 36 + q * 2) = u;
        }
        __syncthreads();

        {
            float c[8][4];
#pragma unroll
            for (int nt = 0; nt < 8; nt++) {
                const float2 bb = *(const float2*)(bs1 + nt * 8 + 2 * t);
                c[nt][0] = bb.x; c[nt][1] = bb.y; c[nt][2] = bb.x; c[nt][3] = bb.y;
            }
#pragma unroll
            for (int kt = 0; kt < 4; kt++) {
                const int kb = kt * 8;
                const unsigned a0 = Xsu[(r0)     * 36 + kb + t];
                const unsigned a1 = Xsu[(r0 + 8) * 36 + kb + t];
                const unsigned a2 = Xsu[(r0)     * 36 + kb + t + 4];
                const unsigned a3 = Xsu[(r0 + 8) * 36 + kb + t + 4];
#pragma unroll
                for (int nt = 0; nt < 8; nt++) {
                    const unsigned b0r = W1u[(nt * 8 + g) * 36 + kb + t];
                    const unsigned b1r = W1u[(nt * 8 + g) * 36 + kb + t + 4];
                    mma16(c[nt], a0, a1, a2, a3, b0r, b1r);
                }
            }
#pragma unroll
            for (int nt = 0; nt < 8; nt++) {
                Ysu[(r0)     * 36 + nt * 4 + t] =
                    packh2(fmaxf(c[nt][0], 0.f), fmaxf(c[nt][1], 0.f));
                Ysu[(r0 + 8) * 36 + nt * 4 + t] =
                    packh2(fmaxf(c[nt][2], 0.f), fmaxf(c[nt][3], 0.f));
            }
        }
        __syncthreads();

        {
            float c[8][4];
#pragma unroll
            for (int nt = 0; nt < 8; nt++) {
                const float2 bb = *(const float2*)(bs2 + nt * 8 + 2 * t);
                c[nt][0] = bb.x; c[nt][1] = bb.y; c[nt][2] = bb.x; c[nt][3] = bb.y;
            }
#pragma unroll
            for (int kt = 0; kt < 4; kt++) {
                const int kb = kt * 8;
                const unsigned a0 = Ysu[(r0)     * 36 + kb + t];
                const unsigned a1 = Ysu[(r0 + 8) * 36 + kb + t];
                const unsigned a2 = Ysu[(r0)     * 36 + kb + t + 4];
                const unsigned a3 = Ysu[(r0 + 8) * 36 + kb + t + 4];
#pragma unroll
                for (int nt = 0; nt < 8; nt++) {
                    const unsigned b0r = W2u[(nt * 8 + g) * 36 + kb + t];
                    const unsigned b1r = W2u[(nt * 8 + g) * 36 + kb + t + 4];
                    mma16(c[nt], a0, a1, a2, a3, b0r, b1r);
                }
            }
#pragma unroll
            for (int nt = 0; nt < 8; nt++) {
                Xsu[(r0)     * 36 + nt * 4 + t] =
                    packh2(fmaxf(c[nt][0], 0.f), fmaxf(c[nt][1], 0.f));
                Xsu[(r0 + 8) * 36 + nt * 4 + t] =
                    packh2(fmaxf(c[nt][2], 0.f), fmaxf(c[nt][3], 0.f));
            }
        }
        __syncthreads();

        {
            float c[2][4];
#pragma unroll
            for (int nt = 0; nt < 2; nt++) {
                const float2 bb = *(const float2*)(bs3 + nt * 8 + 2 * t);
                c[nt][0] = bb.x; c[nt][1] = bb.y; c[nt][2] = bb.x; c[nt][3] = bb.y;
            }
#pragma unroll
            for (int kt = 0; kt < 4; kt++) {
                const int kb = kt * 8;
                const unsigned a0 = Xsu[(r0)     * 36 + kb + t];
                const unsigned a1 = Xsu[(r0 + 8) * 36 + kb + t];
                const unsigned a2 = Xsu[(r0)     * 36 + kb + t + 4];
                const unsigned a3 = Xsu[(r0 + 8) * 36 + kb + t + 4];
#pragma unroll
                for (int nt = 0; nt < 2; nt++) {
                    const unsigned b0r = W3u[(nt * 8 + g) * 36 + kb + t];
                    const unsigned b1r = W3u[(nt * 8 + g) * 36 + kb + t + 4];
                    mma16(c[nt], a0, a1, a2, a3, b0r, b1r);
                }
            }
#pragma unroll
            for (int nt = 0; nt < 2; nt++) {
                const int col = nt * 8 + 2 * t;
                *(float2*)(Of + (r0)     * 16 + col) =
                    make_float2(fmaxf(c[nt][0], 0.f), fmaxf(c[nt][1], 0.f));
                *(float2*)(Of + (r0 + 8) * 16 + col) =
                    make_float2(fmaxf(c[nt][2], 0.f), fmaxf(c[nt][3], 0.f));
            }
        }
        __syncthreads();

        if (tid < 64) {
            const int mol = tid >> 4, col = tid & 15;
            float s = 0.f;
#pragma unroll
            for (int rr = 0; rr < 32; rr++) s += Of[(mol * 32 + rr) * 16 + col];
            out[((size_t)tile * 4 + mol) * 16 + col] = s;
        }
    }
}

extern "C" void kernel_launch(void* const* d_in, const int* in_sizes, int n_in,
                              void* d_out, int out_size) {
    const float* atom_states = (const float*)d_in[0];
    const int*   edge_src    = (const int*)d_in[1];
    const int*   edge_dst    = (const int*)d_in[2];
    const float* ms0w = (const float*)d_in[4];  const float* ms0b = (const float*)d_in[5];
    const float* ms1w = (const float*)d_in[6];  const float* ms1b = (const float*)d_in[7];
    const float* ms2w = (const float*)d_in[8];  const float* ms2b = (const float*)d_in[9];
    const float* fc1w = (const float*)d_in[10]; const float* fc1b = (const float*)d_in[11];
    const float* fc2w = (const float*)d_in[12]; const float* fc2b = (const float*)d_in[13];
    const float* outw = (const float*)d_in[14]; const float* outb = (const float*)d_in[15];
    float* out = (float*)d_out;

    cudaFuncSetAttribute(pq_kernel, cudaFuncAttributeMaxDynamicSharedMemorySize, PQ_SMEM_BYTES);
    cudaFuncSetAttribute(edge_kernel, cudaFuncAttributeMaxDynamicSharedMemorySize, EH_SMEM_BYTES);
    cudaFuncSetAttribute(readout_kernel, cudaFuncAttributeMaxDynamicSharedMemorySize, RH_SMEM_BYTES);

    int sms = 148;
    cudaDeviceGetAttribute(&sms, cudaDevAttrMultiProcessorCount, 0);

    pq_kernel<<<2 * sms, 256, PQ_SMEM_BYTES>>>(atom_states, ms0w);
    edge_kernel<<<3 * sms, 256, EH_SMEM_BYTES>>>(edge_src, edge_dst,
                                                 ms0b, ms1w, ms1b, ms2w, ms2b);
    readout_kernel<<<3 * sms, 256, RH_SMEM_BYTES>>>(fc1w, fc1b, fc2w, fc2b,
                                                    outw, outb, out);
}

// round 16
// speedup vs baseline: 1.5424x; 1.5424x over previous
#include <cuda_runtime.h>
#include <cuda_fp16.h>
#include <cstdint>

#define N_ATOMS   131072
#define N_EDGES   1048576
#define DSTATE    64
#define N_MOLS    4096
#define ETILE     128
#define N_ETILES  (N_EDGES / ETILE)   // 8192
#define N_ATILES  (N_ATOMS / 128)     // 1024

__device__ float4 g_new_states4[N_ATOMS * DSTATE / 4];
__device__ uint4  g_Ph4[N_ATOMS * 8];   // P as fp16: 64 halfs = 8 uint4 per atom
__device__ uint4  g_Qh4[N_ATOMS * 8];

__device__ __forceinline__ uint32_t smem_u32(const void* p) {
    uint32_t a;
    asm("{ .reg .u64 t; cvta.to.shared.u64 t, %1; cvt.u32.u64 %0, t; }" : "=r"(a) : "l"(p));
    return a;
}

// fp16 m16n8k16, fp32 accum
__device__ __forceinline__ void mma16(float* c, unsigned a0, unsigned a1,
                                      unsigned a2, unsigned a3,
                                      unsigned b0, unsigned b1) {
    asm volatile(
        "mma.sync.aligned.m16n8k16.row.col.f32.f16.f16.f32 "
        "{%0,%1,%2,%3}, {%4,%5,%6,%7}, {%8,%9}, {%0,%1,%2,%3};"
        : "+f"(c[0]), "+f"(c[1]), "+f"(c[2]), "+f"(c[3])
        : "r"(a0), "r"(a1), "r"(a2), "r"(a3), "r"(b0), "r"(b1));
}

__device__ __forceinline__ unsigned packh2(float lo, float hi) {
    __half2 h = __floats2half2_rn(lo, hi);
    return *(unsigned*)&h;
}

__device__ __forceinline__ void cp16(uint32_t dst, const void* src) {
    asm volatile("cp.async.cg.shared.global [%0], [%1], 16;" :: "r"(dst), "l"(src));
}
__device__ __forceinline__ void cp_commit() { asm volatile("cp.async.commit_group;" ::: "memory"); }
__device__ __forceinline__ void cp_wait0()  { asm volatile("cp.async.wait_group 0;" ::: "memory"); }
__device__ __forceinline__ void cp_wait1()  { asm volatile("cp.async.wait_group 1;" ::: "memory"); }

// ====================== P/Q precompute kernel (R14 version: cp.async staging) ======================
#define PQ_XR0  0
#define PQ_XR1  8704
#define PQ_W    17408                 // uints region: 2 x 64*36
#define PQ_SMEM_FLOATS (PQ_W + 2*64*36)
#define PQ_SMEM_BYTES  (PQ_SMEM_FLOATS * 4)

__device__ __forceinline__ void pq_layer_h16(
    const float* __restrict__ Xr, const unsigned* __restrict__ Wu,
    unsigned* __restrict__ gOut, int warp, int g, int t)
{
    float c[8][4];
#pragma unroll
    for (int nt = 0; nt < 8; nt++)
        c[nt][0] = c[nt][1] = c[nt][2] = c[nt][3] = 0.f;
    const int row0 = warp * 16 + g;
#pragma unroll
    for (int kt = 0; kt < 4; kt++) {
        const int kb = kt * 8;
        const int k0 = 2 * (kb + t), k1 = 2 * (kb + t + 4);
        const float2 f0 = *(const float2*)(Xr + (row0)     * 68 + k0);
        const float2 f1 = *(const float2*)(Xr + (row0 + 8) * 68 + k0);
        const float2 f2 = *(const float2*)(Xr + (row0)     * 68 + k1);
        const float2 f3 = *(const float2*)(Xr + (row0 + 8) * 68 + k1);
        const unsigned a0 = packh2(f0.x, f0.y);
        const unsigned a1 = packh2(f1.x, f1.y);
        const unsigned a2 = packh2(f2.x, f2.y);
        const unsigned a3 = packh2(f3.x, f3.y);
#pragma unroll
        for (int nt = 0; nt < 8; nt++) {
            const unsigned b0 = Wu[(nt * 8 + g) * 36 + kb + t];
            const unsigned b1 = Wu[(nt * 8 + g) * 36 + kb + t + 4];
            mma16(c[nt], a0, a1, a2, a3, b0, b1);
        }
    }
#pragma unroll
    for (int nt = 0; nt < 8; nt++) {
        gOut[(size_t)(row0)     * 32 + nt * 4 + t] = packh2(c[nt][0], c[nt][1]);
        gOut[(size_t)(row0 + 8) * 32 + nt * 4 + t] = packh2(c[nt][2], c[nt][3]);
    }
}

__global__ void __launch_bounds__(256, 2) pq_kernel(
    const float* __restrict__ atom_states,
    const float* __restrict__ w0)
{
    extern __shared__ float sm[];
    unsigned* Wt = (unsigned*)(sm + PQ_W);
    unsigned* Wb = Wt + 64 * 36;
    const uint32_t base = smem_u32(sm);

    const int tid  = threadIdx.x;
    const int warp = tid >> 5, lane = tid & 31;
    const int g = lane >> 2, t = lane & 3;
    const int stride = gridDim.x;

    for (int i = tid; i < 64 * 64; i += 256) {
        int k = i >> 6, n = i & 63;
        ((__half*)Wt)[n * 72 + k] = __float2half_rn(w0[k * 64 + n]);
        ((__half*)Wb)[n * 72 + k] = __float2half_rn(w0[(k + 64) * 64 + n]);
    }

    if (blockIdx.x < N_ATILES) {
        const float* src = atom_states + (size_t)blockIdx.x * 128 * 64;
#pragma unroll
        for (int c = 0; c < 8; c++) {
            int id = c * 256 + tid;
            int row = id >> 4, off = id & 15;
            cp16(base + (uint32_t)(PQ_XR0 + row * 68 + off * 4) * 4u,
                 src + (size_t)row * 64 + off * 4);
        }
        cp_commit();
    }

    int it = 0;
    for (int tile = blockIdx.x; tile < N_ATILES; tile += stride, it++) {
        const int tn = tile + stride;
        if (tn < N_ATILES) {
            const float* src = atom_states + (size_t)tn * 128 * 64;
            const uint32_t dbuf = ((it + 1) & 1) ? PQ_XR1 : PQ_XR0;
#pragma unroll
            for (int c = 0; c < 8; c++) {
                int id = c * 256 + tid;
                int row = id >> 4, off = id & 15;
                cp16(base + (dbuf + (uint32_t)(row * 68 + off * 4)) * 4u,
                     src + (size_t)row * 64 + off * 4);
            }
            cp_commit();
            cp_wait1();
        } else {
            cp_wait0();
        }
        __syncthreads();

        const float* Xr = sm + ((it & 1) ? PQ_XR1 : PQ_XR0);
        unsigned* gP = (unsigned*)g_Ph4 + (size_t)tile * 128 * 32;
        unsigned* gQ = (unsigned*)g_Qh4 + (size_t)tile * 128 * 32;
        pq_layer_h16(Xr, Wt, gP, warp, g, t);
        pq_layer_h16(Xr, Wb, gQ, warp, g, t);

        float4* gz = g_new_states4 + (size_t)tile * 128 * 16;
        const float4 z = make_float4(0.f, 0.f, 0.f, 0.f);
        for (int i = tid; i < 128 * 16; i += 256) gz[i] = z;
        __syncthreads();
    }
}

// ====================== edge kernel (R14 + half2-native gather staging) ======================
#define EH_A0   0
#define EH_YS   (128*36)
#define EH_W1   (EH_YS + 128*36)
#define EH_W2   (EH_W1 + 64*36)
#define EH_B0H  (EH_W2 + 64*36)      // 32 uints = half2[32] (b0 in half2)
#define EH_B1   (EH_B0H + 32)        // 64 floats
#define EH_B2   (EH_B1 + 64)
#define EH_DST  (EH_B2 + 64)
#define EH_SRC  (EH_DST + 128)
#define EH_UINTS (EH_SRC + 128)
#define EH_SMEM_BYTES (EH_UINTS * 4)

__global__ void __launch_bounds__(256, 3) edge_kernel(
    const int* __restrict__ edge_src,
    const int* __restrict__ edge_dst,
    const float* __restrict__ b0,
    const float* __restrict__ w1, const float* __restrict__ b1,
    const float* __restrict__ w2, const float* __restrict__ b2)
{
    extern __shared__ unsigned smu[];
    unsigned* A0u = smu + EH_A0;
    unsigned* Ysu = smu + EH_YS;
    unsigned* W1u = smu + EH_W1;
    unsigned* W2u = smu + EH_W2;
    __half2* b0h = (__half2*)(smu + EH_B0H);
    float* bs1 = (float*)(smu + EH_B1);
    float* bs2 = (float*)(smu + EH_B2);
    int* sdst = (int*)(smu + EH_DST);
    int* ssrc = (int*)(smu + EH_SRC);

    const int tid  = threadIdx.x;
    const int warp = tid >> 5, lane = tid & 31;
    const int g = lane >> 2, t = lane & 3;
    const int wbase = warp * 16;

    for (int i = tid; i < 64 * 64; i += 256) {
        int k = i >> 6, n = i & 63;
        ((__half*)W1u)[n * 72 + k] = __float2half_rn(w1[i]);
        ((__half*)W2u)[n * 72 + k] = __float2half_rn(w2[i]);
    }
    if (tid < 32) b0h[tid] = __floats2half2_rn(b0[2 * tid], b0[2 * tid + 1]);
    if (tid < 64) { bs1[tid] = b1[tid]; bs2[tid] = b2[tid]; }
    __syncthreads();   // only block barrier

    const uint4* gP = g_Ph4;
    const uint4* gQ = g_Qh4;
    float* g_new = (float*)g_new_states4;
    const __half2 zero2 = __float2half2_rn(0.f);

    for (int tile = blockIdx.x; tile < N_ETILES; tile += gridDim.x) {
        const int e0 = tile * ETILE + wbase;

        if (lane < 16)      sdst[wbase + lane]        = edge_dst[e0 + lane];
        else                ssrc[wbase + (lane - 16)] = edge_src[e0 + lane - 16];
        __syncwarp();

        // ---- gather + stage (half2-native): A0 = hmax(P + Q + b0, 0) ----
#pragma unroll
        for (int c = 0; c < 4; c++) {
            const int i = c * 32 + lane;
            const int rl = i >> 3, q = i & 7;
            const int r = wbase + rl;
            const uint4 pu = gP[(size_t)sdst[r] * 8 + q];
            const uint4 su = gQ[(size_t)ssrc[r] * 8 + q];
            const __half2* ph = (const __half2*)&pu;
            const __half2* sh = (const __half2*)&su;
            uint4 o;
            __half2* oh = (__half2*)&o;
#pragma unroll
            for (int j = 0; j < 4; j++)
                oh[j] = __hmax2(__hadd2(__hadd2(ph[j], sh[j]), b0h[q * 4 + j]), zero2);
            *(uint4*)(A0u + (size_t)r * 36 + q * 4) = o;
        }
        __syncwarp();

        const int r0 = wbase + g;

        // ---- L1 (fp16 k16): A0 -> Ys ----
        {
            float c[8][4];
#pragma unroll
            for (int nt = 0; nt < 8; nt++) {
                const float2 bb = *(const float2*)(bs1 + nt * 8 + 2 * t);
                c[nt][0] = bb.x; c[nt][1] = bb.y; c[nt][2] = bb.x; c[nt][3] = bb.y;
            }
#pragma unroll
            for (int kt = 0; kt < 4; kt++) {
                const int kb = kt * 8;
                const unsigned a0 = A0u[(r0)     * 36 + kb + t];
                const unsigned a1 = A0u[(r0 + 8) * 36 + kb + t];
                const unsigned a2 = A0u[(r0)     * 36 + kb + t + 4];
                const unsigned a3 = A0u[(r0 + 8) * 36 + kb + t + 4];
#pragma unroll
                for (int nt = 0; nt < 8; nt++) {
                    const unsigned b0r = W1u[(nt * 8 + g) * 36 + kb + t];
                    const unsigned b1r = W1u[(nt * 8 + g) * 36 + kb + t + 4];
                    mma16(c[nt], a0, a1, a2, a3, b0r, b1r);
                }
            }
#pragma unroll
            for (int nt = 0; nt < 8; nt++) {
                Ysu[(r0)     * 36 + nt * 4 + t] =
                    packh2(fmaxf(c[nt][0], 0.f), fmaxf(c[nt][1], 0.f));
                Ysu[(r0 + 8) * 36 + nt * 4 + t] =
                    packh2(fmaxf(c[nt][2], 0.f), fmaxf(c[nt][3], 0.f));
            }
        }
        __syncwarp();

        // ---- L2 (fp16 k16): Ys -> C; relu; direct red.v2 scatter ----
        {
            float c[8][4];
#pragma unroll
            for (int nt = 0; nt < 8; nt++) {
                const float2 bb = *(const float2*)(bs2 + nt * 8 + 2 * t);
                c[nt][0] = bb.x; c[nt][1] = bb.y; c[nt][2] = bb.x; c[nt][3] = bb.y;
            }
#pragma unroll
            for (int kt = 0; kt < 4; kt++) {
                const int kb = kt * 8;
                const unsigned a0 = Ysu[(r0)     * 36 + kb + t];
                const unsigned a1 = Ysu[(r0 + 8) * 36 + kb + t];
                const unsigned a2 = Ysu[(r0)     * 36 + kb + t + 4];
                const unsigned a3 = Ysu[(r0 + 8) * 36 + kb + t + 4];
#pragma unroll
                for (int nt = 0; nt < 8; nt++) {
                    const unsigned b0r = W2u[(nt * 8 + g) * 36 + kb + t];
                    const unsigned b1r = W2u[(nt * 8 + g) * 36 + kb + t + 4];
                    mma16(c[nt], a0, a1, a2, a3, b0r, b1r);
                }
            }
            const int da = sdst[r0], db = sdst[r0 + 8];
#pragma unroll
            for (int nt = 0; nt < 8; nt++) {
                const int col = nt * 8 + 2 * t;
                const float v0 = fmaxf(c[nt][0], 0.f), v1 = fmaxf(c[nt][1], 0.f);
                const float v2 = fmaxf(c[nt][2], 0.f), v3 = fmaxf(c[nt][3], 0.f);
                asm volatile("red.global.add.v2.f32 [%0], {%1,%2};"
                             :: "l"(g_new + (size_t)da * 64 + col), "f"(v0), "f"(v1) : "memory");
                asm volatile("red.global.add.v2.f32 [%0], {%1,%2};"
                             :: "l"(g_new + (size_t)db * 64 + col), "f"(v2), "f"(v3) : "memory");
            }
        }
        __syncwarp();
    }
}

// ====================== readout kernel (fp16, R14 version) ======================
#define RH_XS   0
#define RH_YS   (128*36)
#define RH_W1   (RH_YS + 128*36)
#define RH_W2   (RH_W1 + 64*36)
#define RH_W3   (RH_W2 + 64*36)
#define RH_B1   (RH_W3 + 16*36)
#define RH_B2   (RH_B1 + 64)
#define RH_B3   (RH_B2 + 64)
#define RH_UINTS (RH_B3 + 16)
#define RH_SMEM_BYTES (RH_UINTS * 4)

__global__ void __launch_bounds__(256, 3) readout_kernel(
    const float* __restrict__ fc1w, const float* __restrict__ fc1b,
    const float* __restrict__ fc2w, const float* __restrict__ fc2b,
    const float* __restrict__ outw, const float* __restrict__ outb,
    float* __restrict__ out)
{
    extern __shared__ unsigned smu[];
    unsigned* Xsu = smu + RH_XS;
    unsigned* Ysu = smu + RH_YS;
    float*    Of  = (float*)(smu + RH_YS);
    unsigned* W1u = smu + RH_W1;
    unsigned* W2u = smu + RH_W2;
    unsigned* W3u = smu + RH_W3;
    float* bs1 = (float*)(smu + RH_B1);
    float* bs2 = (float*)(smu + RH_B2);
    float* bs3 = (float*)(smu + RH_B3);

    const int tid  = threadIdx.x;
    const int warp = tid >> 5, lane = tid & 31;
    const int g = lane >> 2, t = lane & 3;

    for (int i = tid; i < 64 * 64; i += 256) {
        int k = i >> 6, n = i & 63;
        ((__half*)W1u)[n * 72 + k] = __float2half_rn(fc1w[i]);
        ((__half*)W2u)[n * 72 + k] = __float2half_rn(fc2w[i]);
    }
    for (int i = tid; i < 64 * 16; i += 256) {
        int k = i >> 4, n = i & 15;
        ((__half*)W3u)[n * 72 + k] = __float2half_rn(outw[i]);
    }
    if (tid < 64) { bs1[tid] = fc1b[tid]; bs2[tid] = fc2b[tid]; }
    if (tid < 16) bs3[tid] = outb[tid];

    const float* g_new = (const float*)g_new_states4;
    const int r0 = warp * 16 + g;

    for (int tile = blockIdx.x; tile < N_ATILES; tile += gridDim.x) {
        __syncthreads();
        for (int i = tid; i < 128 * 16; i += 256) {
            const int rr = i >> 4, q = i & 15;
            const float4 v = *(const float4*)(g_new + ((size_t)tile * 128 + rr) * 64 + q * 4);
            uint2 u;
            u.x = packh2(v.x, v.y);
            u.y = packh2(v.z, v.w);
            *(uint2*)(Xsu + (size_t)rr * 36 + q * 2) = u;
        }
        __syncthreads();

        {
            float c[8][4];
#pragma unroll
            for (int nt = 0; nt < 8; nt++) {
                const float2 bb = *(const float2*)(bs1 + nt * 8 + 2 * t);
                c[nt][0] = bb.x; c[nt][1] = bb.y; c[nt][2] = bb.x; c[nt][3] = bb.y;
            }
#pragma unroll
            for (int kt = 0; kt < 4; kt++) {
                const int kb = kt * 8;
                const unsigned a0 = Xsu[(r0)     * 36 + kb + t];
                const unsigned a1 = Xsu[(r0 + 8) * 36 + kb + t];
                const unsigned a2 = Xsu[(r0)     * 36 + kb + t + 4];
                const unsigned a3 = Xsu[(r0 + 8) * 36 + kb + t + 4];
#pragma unroll
                for (int nt = 0; nt < 8; nt++) {
                    const unsigned b0r = W1u[(nt * 8 + g) * 36 + kb + t];
                    const unsigned b1r = W1u[(nt * 8 + g) * 36 + kb + t + 4];
                    mma16(c[nt], a0, a1, a2, a3, b0r, b1r);
                }
            }
#pragma unroll
            for (int nt = 0; nt < 8; nt++) {
                Ysu[(r0)     * 36 + nt * 4 + t] =
                    packh2(fmaxf(c[nt][0], 0.f), fmaxf(c[nt][1], 0.f));
                Ysu[(r0 + 8) * 36 + nt * 4 + t] =
                    packh2(fmaxf(c[nt][2], 0.f), fmaxf(c[nt][3], 0.f));
            }
        }
        __syncthreads();

        {
            float c[8][4];
#pragma unroll
            for (int nt = 0; nt < 8; nt++) {
                const float2 bb = *(const float2*)(bs2 + nt * 8 + 2 * t);
                c[nt][0] = bb.x; c[nt][1] = bb.y; c[nt][2] = bb.x; c[nt][3] = bb.y;
            }
#pragma unroll
            for (int kt = 0; kt < 4; kt++) {
                const int kb = kt * 8;
                const unsigned a0 = Ysu[(r0)     * 36 + kb + t];
                const unsigned a1 = Ysu[(r0 + 8) * 36 + kb + t];
                const unsigned a2 = Ysu[(r0)     * 36 + kb + t + 4];
                const unsigned a3 = Ysu[(r0 + 8) * 36 + kb + t + 4];
#pragma unroll
                for (int nt = 0; nt < 8; nt++) {
                    const unsigned b0r = W2u[(nt * 8 + g) * 36 + kb + t];
                    const unsigned b1r = W2u[(nt * 8 + g) * 36 + kb + t + 4];
                    mma16(c[nt], a0, a1, a2, a3, b0r, b1r);
                }
            }
#pragma unroll
            for (int nt = 0; nt < 8; nt++) {
                Xsu[(r0)     * 36 + nt * 4 + t] =
                    packh2(fmaxf(c[nt][0], 0.f), fmaxf(c[nt][1], 0.f));
                Xsu[(r0 + 8) * 36 + nt * 4 + t] =
                    packh2(fmaxf(c[nt][2], 0.f), fmaxf(c[nt][3], 0.f));
            }
        }
        __syncthreads();

        {
            float c[2][4];
#pragma unroll
            for (int nt = 0; nt < 2; nt++) {
                const float2 bb = *(const float2*)(bs3 + nt * 8 + 2 * t);
                c[nt][0] = bb.x; c[nt][1] = bb.y; c[nt][2] = bb.x; c[nt][3] = bb.y;
            }
#pragma unroll
            for (int kt = 0; kt < 4; kt++) {
                const int kb = kt * 8;
                const unsigned a0 = Xsu[(r0)     * 36 + kb + t];
                const unsigned a1 = Xsu[(r0 + 8) * 36 + kb + t];
                const unsigned a2 = Xsu[(r0)     * 36 + kb + t + 4];
                const unsigned a3 = Xsu[(r0 + 8) * 36 + kb + t + 4];
#pragma unroll
                for (int nt = 0; nt < 2; nt++) {
                    const unsigned b0r = W3u[(nt * 8 + g) * 36 + kb + t];
                    const unsigned b1r = W3u[(nt * 8 + g) * 36 + kb + t + 4];
                    mma16(c[nt], a0, a1, a2, a3, b0r, b1r);
                }
            }
#pragma unroll
            for (int nt = 0; nt < 2; nt++) {
                const int col = nt * 8 + 2 * t;
                *(float2*)(Of + (r0)     * 16 + col) =
                    make_float2(fmaxf(c[nt][0], 0.f), fmaxf(c[nt][1], 0.f));
                *(float2*)(Of + (r0 + 8) * 16 + col) =
                    make_float2(fmaxf(c[nt][2], 0.f), fmaxf(c[nt][3], 0.f));
            }
        }
        __syncthreads();

        if (tid < 64) {
            const int mol = tid >> 4, col = tid & 15;
            float s = 0.f;
#pragma unroll
            for (int rr = 0; rr < 32; rr++) s += Of[(mol * 32 + rr) * 16 + col];
            out[((size_t)tile * 4 + mol) * 16 + col] = s;
        }
    }
}

extern "C" void kernel_launch(void* const* d_in, const int* in_sizes, int n_in,
                              void* d_out, int out_size) {
    const float* atom_states = (const float*)d_in[0];
    const int*   edge_src    = (const int*)d_in[1];
    const int*   edge_dst    = (const int*)d_in[2];
    const float* ms0w = (const float*)d_in[4];  const float* ms0b = (const float*)d_in[5];
    const float* ms1w = (const float*)d_in[6];  const float* ms1b = (const float*)d_in[7];
    const float* ms2w = (const float*)d_in[8];  const float* ms2b = (const float*)d_in[9];
    const float* fc1w = (const float*)d_in[10]; const float* fc1b = (const float*)d_in[11];
    const float* fc2w = (const float*)d_in[12]; const float* fc2b = (const float*)d_in[13];
    const float* outw = (const float*)d_in[14]; const float* outb = (const float*)d_in[15];
    float* out = (float*)d_out;

    cudaFuncSetAttribute(pq_kernel, cudaFuncAttributeMaxDynamicSharedMemorySize, PQ_SMEM_BYTES);
    cudaFuncSetAttribute(edge_kernel, cudaFuncAttributeMaxDynamicSharedMemorySize, EH_SMEM_BYTES);
    cudaFuncSetAttribute(readout_kernel, cudaFuncAttributeMaxDynamicSharedMemorySize, RH_SMEM_BYTES);

    int sms = 148;
    cudaDeviceGetAttribute(&sms, cudaDevAttrMultiProcessorCount, 0);

    pq_kernel<<<2 * sms, 256, PQ_SMEM_BYTES>>>(atom_states, ms0w);
    edge_kernel<<<3 * sms, 256, EH_SMEM_BYTES>>>(edge_src, edge_dst,
                                                 ms0b, ms1w, ms1b, ms2w, ms2b);
    readout_kernel<<<3 * sms, 256, RH_SMEM_BYTES>>>(fc1w, fc1b, fc2w, fc2b,
                                                    outw, outb, out);
}

// round 17
// speedup vs baseline: 1.5590x; 1.0108x over previous
#include <cuda_runtime.h>
#include <cuda_fp16.h>
#include <cstdint>

#define N_ATOMS   131072
#define N_EDGES   1048576
#define DSTATE    64
#define N_MOLS    4096
#define ETILE     128
#define N_ETILES  (N_EDGES / ETILE)   // 8192
#define N_ATILES  (N_ATOMS / 128)     // 1024

__device__ float4 g_new_states4[N_ATOMS * DSTATE / 4];
__device__ uint4  g_Ph4[N_ATOMS * 8];   // P as fp16: 64 halfs = 8 uint4 per atom
__device__ uint4  g_Qh4[N_ATOMS * 8];

__device__ __forceinline__ uint32_t smem_u32(const void* p) {
    uint32_t a;
    asm("{ .reg .u64 t; cvta.to.shared.u64 t, %1; cvt.u32.u64 %0, t; }" : "=r"(a) : "l"(p));
    return a;
}

// fp16 m16n8k16, fp32 accum
__device__ __forceinline__ void mma16(float* c, unsigned a0, unsigned a1,
                                      unsigned a2, unsigned a3,
                                      unsigned b0, unsigned b1) {
    asm volatile(
        "mma.sync.aligned.m16n8k16.row.col.f32.f16.f16.f32 "
        "{%0,%1,%2,%3}, {%4,%5,%6,%7}, {%8,%9}, {%0,%1,%2,%3};"
        : "+f"(c[0]), "+f"(c[1]), "+f"(c[2]), "+f"(c[3])
        : "r"(a0), "r"(a1), "r"(a2), "r"(a3), "r"(b0), "r"(b1));
}

__device__ __forceinline__ unsigned packh2(float lo, float hi) {
    __half2 h = __floats2half2_rn(lo, hi);
    return *(unsigned*)&h;
}

__device__ __forceinline__ void cp16(uint32_t dst, const void* src) {
    asm volatile("cp.async.cg.shared.global [%0], [%1], 16;" :: "r"(dst), "l"(src));
}
__device__ __forceinline__ void cp_commit() { asm volatile("cp.async.commit_group;" ::: "memory"); }
__device__ __forceinline__ void cp_wait0()  { asm volatile("cp.async.wait_group 0;" ::: "memory"); }
__device__ __forceinline__ void cp_wait1()  { asm volatile("cp.async.wait_group 1;" ::: "memory"); }

// ====================== P/Q precompute kernel: cp.async staging + MERGED P/Q mma ======================
#define PQ_XR0  0
#define PQ_XR1  8704
#define PQ_W    17408                 // uints region: 2 x 64*36
#define PQ_SMEM_FLOATS (PQ_W + 2*64*36)
#define PQ_SMEM_BYTES  (PQ_SMEM_FLOATS * 4)

__global__ void __launch_bounds__(256, 2) pq_kernel(
    const float* __restrict__ atom_states,
    const float* __restrict__ w0)
{
    extern __shared__ float sm[];
    unsigned* Wt = (unsigned*)(sm + PQ_W);
    unsigned* Wb = Wt + 64 * 36;
    const uint32_t base = smem_u32(sm);

    const int tid  = threadIdx.x;
    const int warp = tid >> 5, lane = tid & 31;
    const int g = lane >> 2, t = lane & 3;
    const int stride = gridDim.x;

    for (int i = tid; i < 64 * 64; i += 256) {
        int k = i >> 6, n = i & 63;
        ((__half*)Wt)[n * 72 + k] = __float2half_rn(w0[k * 64 + n]);
        ((__half*)Wb)[n * 72 + k] = __float2half_rn(w0[(k + 64) * 64 + n]);
    }

    if (blockIdx.x < N_ATILES) {
        const float* src = atom_states + (size_t)blockIdx.x * 128 * 64;
#pragma unroll
        for (int c = 0; c < 8; c++) {
            int id = c * 256 + tid;
            int row = id >> 4, off = id & 15;
            cp16(base + (uint32_t)(PQ_XR0 + row * 68 + off * 4) * 4u,
                 src + (size_t)row * 64 + off * 4);
        }
        cp_commit();
    }

    unsigned* gPb = (unsigned*)g_Ph4;
    unsigned* gQb = (unsigned*)g_Qh4;

    int it = 0;
    for (int tile = blockIdx.x; tile < N_ATILES; tile += stride, it++) {
        const int tn = tile + stride;
        if (tn < N_ATILES) {
            const float* src = atom_states + (size_t)tn * 128 * 64;
            const uint32_t dbuf = ((it + 1) & 1) ? PQ_XR1 : PQ_XR0;
#pragma unroll
            for (int c = 0; c < 8; c++) {
                int id = c * 256 + tid;
                int row = id >> 4, off = id & 15;
                cp16(base + (dbuf + (uint32_t)(row * 68 + off * 4)) * 4u,
                     src + (size_t)row * 64 + off * 4);
            }
            cp_commit();
            cp_wait1();
        } else {
            cp_wait0();
        }
        __syncthreads();

        const float* Xr = sm + ((it & 1) ? PQ_XR1 : PQ_XR0);
        const int row0 = warp * 16 + g;

        // merged: load/pack each A-fragment once, feed both weight chains
        float cP[8][4], cQ[8][4];
#pragma unroll
        for (int nt = 0; nt < 8; nt++) {
            cP[nt][0] = cP[nt][1] = cP[nt][2] = cP[nt][3] = 0.f;
            cQ[nt][0] = cQ[nt][1] = cQ[nt][2] = cQ[nt][3] = 0.f;
        }
#pragma unroll
        for (int kt = 0; kt < 4; kt++) {
            const int kb = kt * 8;
            const int k0 = 2 * (kb + t), k1 = 2 * (kb + t + 4);
            const float2 f0 = *(const float2*)(Xr + (row0)     * 68 + k0);
            const float2 f1 = *(const float2*)(Xr + (row0 + 8) * 68 + k0);
            const float2 f2 = *(const float2*)(Xr + (row0)     * 68 + k1);
            const float2 f3 = *(const float2*)(Xr + (row0 + 8) * 68 + k1);
            const unsigned a0 = packh2(f0.x, f0.y);
            const unsigned a1 = packh2(f1.x, f1.y);
            const unsigned a2 = packh2(f2.x, f2.y);
            const unsigned a3 = packh2(f3.x, f3.y);
#pragma unroll
            for (int nt = 0; nt < 8; nt++) {
                const unsigned bt0 = Wt[(nt * 8 + g) * 36 + kb + t];
                const unsigned bt1 = Wt[(nt * 8 + g) * 36 + kb + t + 4];
                mma16(cP[nt], a0, a1, a2, a3, bt0, bt1);
                const unsigned bb0 = Wb[(nt * 8 + g) * 36 + kb + t];
                const unsigned bb1 = Wb[(nt * 8 + g) * 36 + kb + t + 4];
                mma16(cQ[nt], a0, a1, a2, a3, bb0, bb1);
            }
        }
        unsigned* gP = gPb + (size_t)tile * 128 * 32;
        unsigned* gQ = gQb + (size_t)tile * 128 * 32;
#pragma unroll
        for (int nt = 0; nt < 8; nt++) {
            gP[(size_t)(row0)     * 32 + nt * 4 + t] = packh2(cP[nt][0], cP[nt][1]);
            gP[(size_t)(row0 + 8) * 32 + nt * 4 + t] = packh2(cP[nt][2], cP[nt][3]);
            gQ[(size_t)(row0)     * 32 + nt * 4 + t] = packh2(cQ[nt][0], cQ[nt][1]);
            gQ[(size_t)(row0 + 8) * 32 + nt * 4 + t] = packh2(cQ[nt][2], cQ[nt][3]);
        }

        float4* gz = g_new_states4 + (size_t)tile * 128 * 16;
        const float4 z = make_float4(0.f, 0.f, 0.f, 0.f);
        for (int i = tid; i < 128 * 16; i += 256) gz[i] = z;
        __syncthreads();
    }
}

// ====================== edge kernel (unchanged from R16) ======================
#define EH_A0   0
#define EH_YS   (128*36)
#define EH_W1   (EH_YS + 128*36)
#define EH_W2   (EH_W1 + 64*36)
#define EH_B0H  (EH_W2 + 64*36)      // 32 uints = half2[32]
#define EH_B1   (EH_B0H + 32)
#define EH_B2   (EH_B1 + 64)
#define EH_DST  (EH_B2 + 64)
#define EH_SRC  (EH_DST + 128)
#define EH_UINTS (EH_SRC + 128)
#define EH_SMEM_BYTES (EH_UINTS * 4)

__global__ void __launch_bounds__(256, 3) edge_kernel(
    const int* __restrict__ edge_src,
    const int* __restrict__ edge_dst,
    const float* __restrict__ b0,
    const float* __restrict__ w1, const float* __restrict__ b1,
    const float* __restrict__ w2, const float* __restrict__ b2)
{
    extern __shared__ unsigned smu[];
    unsigned* A0u = smu + EH_A0;
    unsigned* Ysu = smu + EH_YS;
    unsigned* W1u = smu + EH_W1;
    unsigned* W2u = smu + EH_W2;
    __half2* b0h = (__half2*)(smu + EH_B0H);
    float* bs1 = (float*)(smu + EH_B1);
    float* bs2 = (float*)(smu + EH_B2);
    int* sdst = (int*)(smu + EH_DST);
    int* ssrc = (int*)(smu + EH_SRC);

    const int tid  = threadIdx.x;
    const int warp = tid >> 5, lane = tid & 31;
    const int g = lane >> 2, t = lane & 3;
    const int wbase = warp * 16;

    for (int i = tid; i < 64 * 64; i += 256) {
        int k = i >> 6, n = i & 63;
        ((__half*)W1u)[n * 72 + k] = __float2half_rn(w1[i]);
        ((__half*)W2u)[n * 72 + k] = __float2half_rn(w2[i]);
    }
    if (tid < 32) b0h[tid] = __floats2half2_rn(b0[2 * tid], b0[2 * tid + 1]);
    if (tid < 64) { bs1[tid] = b1[tid]; bs2[tid] = b2[tid]; }
    __syncthreads();

    const uint4* gP = g_Ph4;
    const uint4* gQ = g_Qh4;
    float* g_new = (float*)g_new_states4;
    const __half2 zero2 = __float2half2_rn(0.f);

    for (int tile = blockIdx.x; tile < N_ETILES; tile += gridDim.x) {
        const int e0 = tile * ETILE + wbase;

        if (lane < 16)      sdst[wbase + lane]        = edge_dst[e0 + lane];
        else                ssrc[wbase + (lane - 16)] = edge_src[e0 + lane - 16];
        __syncwarp();

#pragma unroll
        for (int c = 0; c < 4; c++) {
            const int i = c * 32 + lane;
            const int rl = i >> 3, q = i & 7;
            const int r = wbase + rl;
            const uint4 pu = gP[(size_t)sdst[r] * 8 + q];
            const uint4 su = gQ[(size_t)ssrc[r] * 8 + q];
            const __half2* ph = (const __half2*)&pu;
            const __half2* sh = (const __half2*)&su;
            uint4 o;
            __half2* oh = (__half2*)&o;
#pragma unroll
            for (int j = 0; j < 4; j++)
                oh[j] = __hmax2(__hadd2(__hadd2(ph[j], sh[j]), b0h[q * 4 + j]), zero2);
            *(uint4*)(A0u + (size_t)r * 36 + q * 4) = o;
        }
        __syncwarp();

        const int r0 = wbase + g;

        {
            float c[8][4];
#pragma unroll
            for (int nt = 0; nt < 8; nt++) {
                const float2 bb = *(const float2*)(bs1 + nt * 8 + 2 * t);
                c[nt][0] = bb.x; c[nt][1] = bb.y; c[nt][2] = bb.x; c[nt][3] = bb.y;
            }
#pragma unroll
            for (int kt = 0; kt < 4; kt++) {
                const int kb = kt * 8;
                const unsigned a0 = A0u[(r0)     * 36 + kb + t];
                const unsigned a1 = A0u[(r0 + 8) * 36 + kb + t];
                const unsigned a2 = A0u[(r0)     * 36 + kb + t + 4];
                const unsigned a3 = A0u[(r0 + 8) * 36 + kb + t + 4];
#pragma unroll
                for (int nt = 0; nt < 8; nt++) {
                    const unsigned b0r = W1u[(nt * 8 + g) * 36 + kb + t];
                    const unsigned b1r = W1u[(nt * 8 + g) * 36 + kb + t + 4];
                    mma16(c[nt], a0, a1, a2, a3, b0r, b1r);
                }
            }
#pragma unroll
            for (int nt = 0; nt < 8; nt++) {
                Ysu[(r0)     * 36 + nt * 4 + t] =
                    packh2(fmaxf(c[nt][0], 0.f), fmaxf(c[nt][1], 0.f));
                Ysu[(r0 + 8) * 36 + nt * 4 + t] =
                    packh2(fmaxf(c[nt][2], 0.f), fmaxf(c[nt][3], 0.f));
            }
        }
        __syncwarp();

        {
            float c[8][4];
#pragma unroll
            for (int nt = 0; nt < 8; nt++) {
                const float2 bb = *(const float2*)(bs2 + nt * 8 + 2 * t);
                c[nt][0] = bb.x; c[nt][1] = bb.y; c[nt][2] = bb.x; c[nt][3] = bb.y;
            }
#pragma unroll
            for (int kt = 0; kt < 4; kt++) {
                const int kb = kt * 8;
                const unsigned a0 = Ysu[(r0)     * 36 + kb + t];
                const unsigned a1 = Ysu[(r0 + 8) * 36 + kb + t];
                const unsigned a2 = Ysu[(r0)     * 36 + kb + t + 4];
                const unsigned a3 = Ysu[(r0 + 8) * 36 + kb + t + 4];
#pragma unroll
                for (int nt = 0; nt < 8; nt++) {
                    const unsigned b0r = W2u[(nt * 8 + g) * 36 + kb + t];
                    const unsigned b1r = W2u[(nt * 8 + g) * 36 + kb + t + 4];
                    mma16(c[nt], a0, a1, a2, a3, b0r, b1r);
                }
            }
            const int da = sdst[r0], db = sdst[r0 + 8];
#pragma unroll
            for (int nt = 0; nt < 8; nt++) {
                const int col = nt * 8 + 2 * t;
                const float v0 = fmaxf(c[nt][0], 0.f), v1 = fmaxf(c[nt][1], 0.f);
                const float v2 = fmaxf(c[nt][2], 0.f), v3 = fmaxf(c[nt][3], 0.f);
                asm volatile("red.global.add.v2.f32 [%0], {%1,%2};"
                             :: "l"(g_new + (size_t)da * 64 + col), "f"(v0), "f"(v1) : "memory");
                asm volatile("red.global.add.v2.f32 [%0], {%1,%2};"
                             :: "l"(g_new + (size_t)db * 64 + col), "f"(v2), "f"(v3) : "memory");
            }
        }
        __syncwarp();
    }
}

// ====================== readout kernel (fp16, unchanged from R16) ======================
#define RH_XS   0
#define RH_YS   (128*36)
#define RH_W1   (RH_YS + 128*36)
#define RH_W2   (RH_W1 + 64*36)
#define RH_W3   (RH_W2 + 64*36)
#define RH_B1   (RH_W3 + 16*36)
#define RH_B2   (RH_B1 + 64)
#define RH_B3   (RH_B2 + 64)
#define RH_UINTS (RH_B3 + 16)
#define RH_SMEM_BYTES (RH_UINTS * 4)

__global__ void __launch_bounds__(256, 3) readout_kernel(
    const float* __restrict__ fc1w, const float* __restrict__ fc1b,
    const float* __restrict__ fc2w, const float* __restrict__ fc2b,
    const float* __restrict__ outw, const float* __restrict__ outb,
    float* __restrict__ out)
{
    extern __shared__ unsigned smu[];
    unsigned* Xsu = smu + RH_XS;
    unsigned* Ysu = smu + RH_YS;
    float*    Of  = (float*)(smu + RH_YS);
    unsigned* W1u = smu + RH_W1;
    unsigned* W2u = smu + RH_W2;
    unsigned* W3u = smu + RH_W3;
    float* bs1 = (float*)(smu + RH_B1);
    float* bs2 = (float*)(smu + RH_B2);
    float* bs3 = (float*)(smu + RH_B3);

    const int tid  = threadIdx.x;
    const int warp = tid >> 5, lane = tid & 31;
    const int g = lane >> 2, t = lane & 3;

    for (int i = tid; i < 64 * 64; i += 256) {
        int k = i >> 6, n = i & 63;
        ((__half*)W1u)[n * 72 + k] = __float2half_rn(fc1w[i]);
        ((__half*)W2u)[n * 72 + k] = __float2half_rn(fc2w[i]);
    }
    for (int i = tid; i < 64 * 16; i += 256) {
        int k = i >> 4, n = i & 15;
        ((__half*)W3u)[n * 72 + k] = __float2half_rn(outw[i]);
    }
    if (tid < 64) { bs1[tid] = fc1b[tid]; bs2[tid] = fc2b[tid]; }
    if (tid < 16) bs3[tid] = outb[tid];

    const float* g_new = (const float*)g_new_states4;
    const int r0 = warp * 16 + g;

    for (int tile = blockIdx.x; tile < N_ATILES; tile += gridDim.x) {
        __syncthreads();
        for (int i = tid; i < 128 * 16; i += 256) {
            const int rr = i >> 4, q = i & 15;
            const float4 v = *(const float4*)(g_new + ((size_t)tile * 128 + rr) * 64 + q * 4);
            uint2 u;
            u.x = packh2(v.x, v.y);
            u.y = packh2(v.z, v.w);
            *(uint2*)(Xsu + (size_t)rr * 36 + q * 2) = u;
        }
        __syncthreads();

        {
            float c[8][4];
#pragma unroll
            for (int nt = 0; nt < 8; nt++) {
                const float2 bb = *(const float2*)(bs1 + nt * 8 + 2 * t);
                c[nt][0] = bb.x; c[nt][1] = bb.y; c[nt][2] = bb.x; c[nt][3] = bb.y;
            }
#pragma unroll
            for (int kt = 0; kt < 4; kt++) {
                const int kb = kt * 8;
                const unsigned a0 = Xsu[(r0)     * 36 + kb + t];
                const unsigned a1 = Xsu[(r0 + 8) * 36 + kb + t];
                const unsigned a2 = Xsu[(r0)     * 36 + kb + t + 4];
                const unsigned a3 = Xsu[(r0 + 8) * 36 + kb + t + 4];
#pragma unroll
                for (int nt = 0; nt < 8; nt++) {
                    const unsigned b0r = W1u[(nt * 8 + g) * 36 + kb + t];
                    const unsigned b1r = W1u[(nt * 8 + g) * 36 + kb + t + 4];
                    mma16(c[nt], a0, a1, a2, a3, b0r, b1r);
                }
            }
#pragma unroll
            for (int nt = 0; nt < 8; nt++) {
                Ysu[(r0)     * 36 + nt * 4 + t] =
                    packh2(fmaxf(c[nt][0], 0.f), fmaxf(c[nt][1], 0.f));
                Ysu[(r0 + 8) * 36 + nt * 4 + t] =
                    packh2(fmaxf(c[nt][2], 0.f), fmaxf(c[nt][3], 0.f));
            }
        }
        __syncthreads();

        {
            float c[8][4];
#pragma unroll
            for (int nt = 0; nt < 8; nt++) {
                const float2 bb = *(const float2*)(bs2 + nt * 8 + 2 * t);
                c[nt][0] = bb.x; c[nt][1] = bb.y; c[nt][2] = bb.x; c[nt][3] = bb.y;
            }
#pragma unroll
            for (int kt = 0; kt < 4; kt++) {
                const int kb = kt * 8;
                const unsigned a0 = Ysu[(r0)     * 36 + kb + t];
                const unsigned a1 = Ysu[(r0 + 8) * 36 + kb + t];
                const unsigned a2 = Ysu[(r0)     * 36 + kb + t + 4];
                const unsigned a3 = Ysu[(r0 + 8) * 36 + kb + t + 4];
#pragma unroll
                for (int nt = 0; nt < 8; nt++) {
                    const unsigned b0r = W2u[(nt * 8 + g) * 36 + kb + t];
                    const unsigned b1r = W2u[(nt * 8 + g) * 36 + kb + t + 4];
                    mma16(c[nt], a0, a1, a2, a3, b0r, b1r);
                }
            }
#pragma unroll
            for (int nt = 0; nt < 8; nt++) {
                Xsu[(r0)     * 36 + nt * 4 + t] =
                    packh2(fmaxf(c[nt][0], 0.f), fmaxf(c[nt][1], 0.f));
                Xsu[(r0 + 8) * 36 + nt * 4 + t] =
                    packh2(fmaxf(c[nt][2], 0.f), fmaxf(c[nt][3], 0.f));
            }
        }
        __syncthreads();

        {
            float c[2][4];
#pragma unroll
            for (int nt = 0; nt < 2; nt++) {
                const float2 bb = *(const float2*)(bs3 + nt * 8 + 2 * t);
                c[nt][0] = bb.x; c[nt][1] = bb.y; c[nt][2] = bb.x; c[nt][3] = bb.y;
            }
#pragma unroll
            for (int kt = 0; kt < 4; kt++) {
                const int kb = kt * 8;
                const unsigned a0 = Xsu[(r0)     * 36 + kb + t];
                const unsigned a1 = Xsu[(r0 + 8) * 36 + kb + t];
                const unsigned a2 = Xsu[(r0)     * 36 + kb + t + 4];
                const unsigned a3 = Xsu[(r0 + 8) * 36 + kb + t + 4];
#pragma unroll
                for (int nt = 0; nt < 2; nt++) {
                    const unsigned b0r = W3u[(nt * 8 + g) * 36 + kb + t];
                    const unsigned b1r = W3u[(nt * 8 + g) * 36 + kb + t + 4];
                    mma16(c[nt], a0, a1, a2, a3, b0r, b1r);
                }
            }
#pragma unroll
            for (int nt = 0; nt < 2; nt++) {
                const int col = nt * 8 + 2 * t;
                *(float2*)(Of + (r0)     * 16 + col) =
                    make_float2(fmaxf(c[nt][0], 0.f), fmaxf(c[nt][1], 0.f));
                *(float2*)(Of + (r0 + 8) * 16 + col) =
                    make_float2(fmaxf(c[nt][2], 0.f), fmaxf(c[nt][3], 0.f));
            }
        }
        __syncthreads();

        if (tid < 64) {
            const int mol = tid >> 4, col = tid & 15;
            float s = 0.f;
#pragma unroll
            for (int rr = 0; rr < 32; rr++) s += Of[(mol * 32 + rr) * 16 + col];
            out[((size_t)tile * 4 + mol) * 16 + col] = s;
        }
    }
}

extern "C" void kernel_launch(void* const* d_in, const int* in_sizes, int n_in,
                              void* d_out, int out_size) {
    const float* atom_states = (const float*)d_in[0];
    const int*   edge_src    = (const int*)d_in[1];
    const int*   edge_dst    = (const int*)d_in[2];
    const float* ms0w = (const float*)d_in[4];  const float* ms0b = (const float*)d_in[5];
    const float* ms1w = (const float*)d_in[6];  const float* ms1b = (const float*)d_in[7];
    const float* ms2w = (const float*)d_in[8];  const float* ms2b = (const float*)d_in[9];
    const float* fc1w = (const float*)d_in[10]; const float* fc1b = (const float*)d_in[11];
    const float* fc2w = (const float*)d_in[12]; const float* fc2b = (const float*)d_in[13];
    const float* outw = (const float*)d_in[14]; const float* outb = (const float*)d_in[15];
    float* out = (float*)d_out;

    cudaFuncSetAttribute(pq_kernel, cudaFuncAttributeMaxDynamicSharedMemorySize, PQ_SMEM_BYTES);
    cudaFuncSetAttribute(edge_kernel, cudaFuncAttributeMaxDynamicSharedMemorySize, EH_SMEM_BYTES);
    cudaFuncSetAttribute(readout_kernel, cudaFuncAttributeMaxDynamicSharedMemorySize, RH_SMEM_BYTES);

    int sms = 148;
    cudaDeviceGetAttribute(&sms, cudaDevAttrMultiProcessorCount, 0);

    pq_kernel<<<2 * sms, 256, PQ_SMEM_BYTES>>>(atom_states, ms0w);
    edge_kernel<<<3 * sms, 256, EH_SMEM_BYTES>>>(edge_src, edge_dst,
                                                 ms0b, ms1w, ms1b, ms2w, ms2b);
    readout_kernel<<<3 * sms, 256, RH_SMEM_BYTES>>>(fc1w, fc1b, fc2w, fc2b,
                                                    outw, outb, out);
}